// round 15
// baseline (speedup 1.0000x reference)
#include <cuda_runtime.h>
#include <cstdint>

// jax threefry mode: 1 = threefry_partitionable (jax >= 0.5.0 default), 0 = legacy
#ifndef RNG_PARTITIONABLE
#define RNG_PARTITIONABLE 1
#endif

#define HROWS  32768
#define NC     1000
#define H_COORD 32768000u   // half of 32*2048*1000
#define H_CODE  1048576u    // half of 32*2048*32
#define QCOFF  4194304      // 65536*64
#define NBLK   592          // 4 blocks/SM on 148 SMs: all co-resident
#define NWARP  (NBLK * 8)   // 4736 independent warps

__device__ double g_parts[NWARP];
__device__ unsigned int g_done;   // zero-init; reset by last block each run

// ---------------- threefry2x32 (matches jax) ----------------
__host__ __device__ __forceinline__ uint32_t rotl32(uint32_t x, int r) {
#ifdef __CUDA_ARCH__
    return __funnelshift_l(x, x, r);
#else
    return (x << r) | (x >> (32 - r));
#endif
}

struct U2 { uint32_t x, y; };

// Key-injection schedule: after round-group j, x0 += A[j], x1 += B[j].
struct TFK {
    uint32_t a0, b0, a1, b1, a2, b2, a3, b3, a4, b4, a5, b5;
};

__host__ inline TFK make_tfk(uint32_t k0, uint32_t k1) {
    uint32_t k2 = k0 ^ k1 ^ 0x1BD11BDAu;
    TFK K;
    K.a0 = k0; K.b0 = k1;
    K.a1 = k1; K.b1 = k2 + 1u;
    K.a2 = k2; K.b2 = k0 + 2u;
    K.a3 = k0; K.b3 = k1 + 3u;
    K.a4 = k1; K.b4 = k2 + 4u;
    K.a5 = k2; K.b5 = k0 + 5u;
    return K;
}

__host__ inline U2 tf_host(uint32_t k0, uint32_t k1, uint32_t x0, uint32_t x1) {
    uint32_t k2 = k0 ^ k1 ^ 0x1BD11BDAu;
    x0 += k0; x1 += k1;
#define TFR(r) { x0 += x1; x1 = rotl32(x1, r); x1 ^= x0; }
    TFR(13) TFR(15) TFR(26) TFR(6)
    x0 += k1; x1 += k2 + 1u;
    TFR(17) TFR(29) TFR(16) TFR(24)
    x0 += k2; x1 += k0 + 2u;
    TFR(13) TFR(15) TFR(26) TFR(6)
    x0 += k0; x1 += k1 + 3u;
    TFR(17) TFR(29) TFR(16) TFR(24)
    x0 += k1; x1 += k2 + 4u;
    TFR(13) TFR(15) TFR(26) TFR(6)
    x0 += k2; x1 += k0 + 5u;
#undef TFR
    U2 r; r.x = x0; r.y = x1; return r;
}

// Integer add on the FMA pipe: IMAD r = a*one + b, `one` is an opaque runtime 1.
__device__ __forceinline__ uint32_t addi(uint32_t a, uint32_t b, uint32_t one) {
    uint32_t r;
    asm("mad.lo.u32 %0, %1, %2, %3;" : "=r"(r) : "r"(a), "r"(one), "r"(b));
    return r;
}

// Cipher specialized for x0-start == 0 (partitionable counters). ALL adds
// (round adds + both key injections) go through IMAD (fma pipe); SHF/LOP3
// stay on alu. (Exact R12 schedule — locally optimal per R5/R11/R14.)
__device__ __forceinline__ U2 tf_dev0(uint32_t x1, const TFK K, uint32_t one) {
    uint32_t x0 = K.a0;
    x1 = addi(x1, K.b0, one);
#define TFRD(r) { x0 = addi(x0, x1, one); x1 = rotl32(x1, r) ^ x0; }
    TFRD(13) TFRD(15) TFRD(26) TFRD(6)
    x0 = addi(x0, K.a1, one); x1 = addi(x1, K.b1, one);
    TFRD(17) TFRD(29) TFRD(16) TFRD(24)
    x0 = addi(x0, K.a2, one); x1 = addi(x1, K.b2, one);
    TFRD(13) TFRD(15) TFRD(26) TFRD(6)
    x0 = addi(x0, K.a3, one); x1 = addi(x1, K.b3, one);
    TFRD(17) TFRD(29) TFRD(16) TFRD(24)
    x0 = addi(x0, K.a4, one); x1 = addi(x1, K.b4, one);
    TFRD(13) TFRD(15) TFRD(26) TFRD(6)
    x0 = addi(x0, K.a5, one); x1 = addi(x1, K.b5, one);
#undef TFRD
    U2 r; r.x = x0; r.y = x1; return r;
}

// general device cipher (legacy path)
__device__ __forceinline__ U2 tf_dev(uint32_t x0, uint32_t x1, const TFK K, uint32_t one) {
#define TFRD(r) { x0 = addi(x0, x1, one); x1 = rotl32(x1, r) ^ x0; }
    x0 = addi(x0, K.a0, one); x1 = addi(x1, K.b0, one);
    TFRD(13) TFRD(15) TFRD(26) TFRD(6)
    x0 = addi(x0, K.a1, one); x1 = addi(x1, K.b1, one);
    TFRD(17) TFRD(29) TFRD(16) TFRD(24)
    x0 = addi(x0, K.a2, one); x1 = addi(x1, K.b2, one);
    TFRD(13) TFRD(15) TFRD(26) TFRD(6)
    x0 = addi(x0, K.a3, one); x1 = addi(x1, K.b3, one);
    TFRD(17) TFRD(29) TFRD(16) TFRD(24)
    x0 = addi(x0, K.a4, one); x1 = addi(x1, K.b4, one);
    TFRD(13) TFRD(15) TFRD(26) TFRD(6)
    x0 = addi(x0, K.a5, one); x1 = addi(x1, K.b5, one);
#undef TFRD
    U2 r; r.x = x0; r.y = x1; return r;
}

__device__ __forceinline__ float ex2a(float x) {
    float r; asm("ex2.approx.ftz.f32 %0, %1;" : "=f"(r) : "f"(x)); return r;
}
__device__ __forceinline__ float lg2a(float x) {
    float r; asm("lg2.approx.ftz.f32 %0, %1;" : "=f"(r) : "f"(x)); return r;
}

// ---------------- packed f32x2 helpers (sm_103a) ----------------
__device__ __forceinline__ uint64_t pk2(float lo, float hi) {
    uint64_t r; asm("mov.b64 %0, {%1, %2};" : "=l"(r) : "f"(lo), "f"(hi)); return r;
}
__device__ __forceinline__ void upk2(float& lo, float& hi, uint64_t p) {
    asm("mov.b64 {%0, %1}, %2;" : "=f"(lo), "=f"(hi) : "l"(p));
}
__device__ __forceinline__ uint64_t fma2(uint64_t a, uint64_t b, uint64_t c) {
    uint64_t r; asm("fma.rn.f32x2 %0, %1, %2, %3;" : "=l"(r) : "l"(a), "l"(b), "l"(c)); return r;
}
__device__ __forceinline__ uint64_t add2(uint64_t a, uint64_t b) {
    uint64_t r; asm("add.rn.f32x2 %0, %1, %2;" : "=l"(r) : "l"(a), "l"(b)); return r;
}

// Returns lg2(t), t = 1e-20 - ln(u + 1e-20); gumbel g = -ln2 * lg2(t).
// eps folded into the FMA constant (u + 1e-20 == u in fp32 for nonzero u).
// Poly branch keeps relative accuracy near u==1 where MUFU abs error blows up.
__device__ __forceinline__ float gumbel_lg2t(uint32_t bits, uint32_t one) {
    uint32_t hi = __umulhi(bits, 0x00800000u);           // bits >> 9
    float u = __uint_as_float(addi(hi, 0x3f800000u, one)) - 1.0f;
    float d = 1.0f - u;                        // exact (Sterbenz) for u >= 0.5
    float series = fmaf(d, fmaf(d, fmaf(d, 0.25f, 0.33333334f), 0.5f), 1.0f);
    float t_poly = fmaf(d, series, 1e-20f);    // 1e-20 - ln(1-d), |d|<=1/16
    float t_lf = fmaf(-0.6931471805599453f, lg2a(u), 1e-20f);
    float t = (d <= 0.0625f) ? t_poly : t_lf;  // > 0
    return lg2a(t);
}

__device__ __forceinline__ float bits_to_gumbel(uint32_t bits, uint32_t one) {
    return -0.6931471805599453f * gumbel_lg2t(bits, one);
}

__device__ __forceinline__ float warp_sum(float v) {
    #pragma unroll
    for (int o = 16; o; o >>= 1) v += __shfl_xor_sync(0xffffffffu, v, o);
    return v;
}
__device__ __forceinline__ float grp8_max(float v) {
    v = fmaxf(v, __shfl_xor_sync(0xffffffffu, v, 4));
    v = fmaxf(v, __shfl_xor_sync(0xffffffffu, v, 2));
    v = fmaxf(v, __shfl_xor_sync(0xffffffffu, v, 1));
    return v;
}
__device__ __forceinline__ float grp8_sum(float v) {
    v += __shfl_xor_sync(0xffffffffu, v, 4);
    v += __shfl_xor_sync(0xffffffffu, v, 2);
    v += __shfl_xor_sync(0xffffffffu, v, 1);
    return v;
}

// ---------------- shared-memory (read-only after init) ----------------
// grid stored pre-duplicated for f32x2 math: gA[n] = ((x,x),(y,y)), gB[n] = (z,z)
struct CoordSm {
    ulonglong2 gA[NC];   // 16000 B
    uint64_t   gB[NC];   //  8000 B
    float  Ws[192];
    float  bs[64];
};
struct CodeSm {
    float  lwt[4096];       // 16384 B  [d][ke] transposed lin_ws
    float  emb_s[32 * 17];  //  2176 B
};

// =======================================================================
// One coordinate row-pair per warp. Row pair (l,h) packed into f32x2
// lanes: logits 3 FFMA2, accumulators 4 f32x2 ops (was 6+8 scalar).
// ILP x4 cipher chains; factorized first-softmax KL via shuffles.
// =======================================================================
__device__ __forceinline__ float coord_pair(
    const CoordSm& sm, int rlo,
    const float* __restrict__ inputs, float* __restrict__ out,
    const TFK Kc, uint32_t one)
{
    const int lane = threadIdx.x & 31;
    const int rhi = rlo + HROWS;

    float p0l, p1l, p2l, ccl, p0h, p1h, p2h, cch;
    {
        float il0 = inputs[(size_t)rlo * 64 + lane];
        float il1 = inputs[(size_t)rlo * 64 + 32 + lane];
        float ih0 = inputs[(size_t)rhi * 64 + lane];
        float ih1 = inputs[(size_t)rhi * 64 + 32 + lane];
        float w00 = sm.Ws[lane * 3 + 0], w01 = sm.Ws[lane * 3 + 1], w02 = sm.Ws[lane * 3 + 2];
        float w10 = sm.Ws[(lane + 32) * 3 + 0], w11 = sm.Ws[(lane + 32) * 3 + 1], w12 = sm.Ws[(lane + 32) * 3 + 2];
        float b0 = sm.bs[lane], b1 = sm.bs[lane + 32];

        p0l = warp_sum(fmaf(il0, w00, il1 * w10));
        p1l = warp_sum(fmaf(il0, w01, il1 * w11));
        p2l = warp_sum(fmaf(il0, w02, il1 * w12));
        ccl = warp_sum(fmaf(il0, b0,  il1 * b1));
        p0h = warp_sum(fmaf(ih0, w00, ih1 * w10));
        p1h = warp_sum(fmaf(ih0, w01, ih1 * w11));
        p2h = warp_sum(fmaf(ih0, w02, ih1 * w12));
        cch = warp_sum(fmaf(ih0, b0,  ih1 * b1));
    }

    const float L2E  = 1.4426950408889634f;
    const float HL2E = 0.7213475204444817f;
    const float LN2  = 0.6931471805599453f;
    float M1l = ccl + 1.5f * (fmaxf(p0l, 0.f) + fmaxf(p1l, 0.f) + fmaxf(p2l, 0.f));
    float M1h = cch + 1.5f * (fmaxf(p0h, 0.f) + fmaxf(p1h, 0.f) + fmaxf(p2h, 0.f));

    // fully pre-scaled exponent, packed (l,h): e = exp2(ps.g + cB - lt/2)
    uint64_t ps0p = pk2(p0l * HL2E, p0h * HL2E);
    uint64_t ps1p = pk2(p1l * HL2E, p1h * HL2E);
    uint64_t ps2p = pk2(p2l * HL2E, p2h * HL2E);
    uint64_t cBp  = pk2((ccl - M1l - 16.0f) * HL2E, (cch - M1h - 16.0f) * HL2E);

    // ---- factorized logZ/KL: lanes 0..5 each handle one (row,dim);
    // shared afterwards by shuffles (no smem, no barrier) ----
    float fv = 0.0f;
    {
        int dim = lane >> 1;
        bool hiRow = lane & 1;
        float p = dim == 0 ? (hiRow ? p0h : p0l)
                : dim == 1 ? (hiRow ? p1h : p1l)
                           : (hiRow ? p2h : p2l);
        if (lane < 6) {
            float mx = 1.5f * fmaxf(p, 0.f);
            float P = 0.f, X = 0.f;
            #pragma unroll
            for (int t = 0; t < 10; t++) {
                float xs = (float)t * (float)(1.5 / 9.0);
                float e = ex2a((p * xs - mx) * L2E);
                P += e; X = fmaf(xs, e, X);
            }
            fv = p * (X / P) - LN2 * lg2a(P);   // E_dim - lnP_dim
        }
    }
    float f0 = __shfl_sync(0xffffffffu, fv, 0);
    float f1 = __shfl_sync(0xffffffffu, fv, 1);
    float f2 = __shfl_sync(0xffffffffu, fv, 2);
    float f3 = __shfl_sync(0xffffffffu, fv, 3);
    float f4 = __shfl_sync(0xffffffffu, fv, 4);
    float f5 = __shfl_sync(0xffffffffu, fv, 5);

    uint64_t S2p = 0, gxp = 0, gyp = 0, gzp = 0;   // packed (l,h) accumulators

    uint32_t ia1 = (uint32_t)rlo * 1000u + (uint32_t)lane;
    uint32_t ia2 = ia1 + 32u;
#if RNG_PARTITIONABLE
    uint32_t ib1 = ia1 + H_COORD;
    uint32_t ib2 = ib1 + 32u;
#endif

    // ---- 15 full iterations, no predicates (covers n in [0,960)) ----
    #pragma unroll 1
    for (int t = 0; t < 15; t++) {
        const int n  = lane + (t << 6);
        ulonglong2 g1xy = sm.gA[n];
        uint64_t   g1zz = sm.gB[n];
        ulonglong2 g2xy = sm.gA[n + 32];
        uint64_t   g2zz = sm.gB[n + 32];

        uint64_t fp1 = fma2(ps0p, g1xy.x, fma2(ps1p, g1xy.y, fma2(ps2p, g1zz, cBp)));
        uint64_t fp2 = fma2(ps0p, g2xy.x, fma2(ps1p, g2xy.y, fma2(ps2p, g2zz, cBp)));
        float f1l, f1h, f2l, f2h;
        upk2(f1l, f1h, fp1);
        upk2(f2l, f2h, fp2);

#if RNG_PARTITIONABLE
        U2 A1 = tf_dev0(ia1, Kc, one);
        U2 A2 = tf_dev0(ia2, Kc, one);
        U2 B1 = tf_dev0(ib1, Kc, one);
        U2 B2 = tf_dev0(ib2, Kc, one);
        float lt1l = gumbel_lg2t(A1.x ^ A1.y, one);
        float lt2l = gumbel_lg2t(A2.x ^ A2.y, one);
        float lt1h = gumbel_lg2t(B1.x ^ B1.y, one);
        float lt2h = gumbel_lg2t(B2.x ^ B2.y, one);
        ia1 = addi(ia1, 64u, one); ia2 = addi(ia2, 64u, one);
        ib1 = addi(ib1, 64u, one); ib2 = addi(ib2, 64u, one);
#else
        U2 A1 = tf_dev(ia1, ia1 + H_COORD, Kc, one);
        U2 A2 = tf_dev(ia2, ia2 + H_COORD, Kc, one);
        float lt1l = gumbel_lg2t(A1.x, one), lt1h = gumbel_lg2t(A1.y, one);
        float lt2l = gumbel_lg2t(A2.x, one), lt2h = gumbel_lg2t(A2.y, one);
        ia1 = addi(ia1, 64u, one); ia2 = addi(ia2, 64u, one);
#endif
        uint64_t ep1 = pk2(ex2a(fmaf(lt1l, -0.5f, f1l)), ex2a(fmaf(lt1h, -0.5f, f1h)));
        uint64_t ep2 = pk2(ex2a(fmaf(lt2l, -0.5f, f2l)), ex2a(fmaf(lt2h, -0.5f, f2h)));

        S2p = add2(S2p, ep1);
        gxp = fma2(ep1, g1xy.x, gxp);
        gyp = fma2(ep1, g1xy.y, gyp);
        gzp = fma2(ep1, g1zz, gzp);
        S2p = add2(S2p, ep2);
        gxp = fma2(ep2, g2xy.x, gxp);
        gyp = fma2(ep2, g2xy.y, gyp);
        gzp = fma2(ep2, g2zz, gzp);
    }

    // ---- tail: n in [960,1000): point1 always valid, point2 iff lane<8 ----
    {
        const int n = lane + 960;
        const bool v2 = (lane < 8);
        const int n2 = v2 ? (n + 32) : n;
        ulonglong2 g1xy = sm.gA[n];
        uint64_t   g1zz = sm.gB[n];
        ulonglong2 g2xy = sm.gA[n2];
        uint64_t   g2zz = sm.gB[n2];

        uint64_t fp1 = fma2(ps0p, g1xy.x, fma2(ps1p, g1xy.y, fma2(ps2p, g1zz, cBp)));
        uint64_t fp2 = fma2(ps0p, g2xy.x, fma2(ps1p, g2xy.y, fma2(ps2p, g2zz, cBp)));
        float f1l, f1h, f2l, f2h;
        upk2(f1l, f1h, fp1);
        upk2(f2l, f2h, fp2);

#if RNG_PARTITIONABLE
        U2 A1 = tf_dev0(ia1, Kc, one);
        U2 A2 = tf_dev0(ia2, Kc, one);
        U2 B1 = tf_dev0(ib1, Kc, one);
        U2 B2 = tf_dev0(ib2, Kc, one);
        float lt1l = gumbel_lg2t(A1.x ^ A1.y, one);
        float lt2l = gumbel_lg2t(A2.x ^ A2.y, one);
        float lt1h = gumbel_lg2t(B1.x ^ B1.y, one);
        float lt2h = gumbel_lg2t(B2.x ^ B2.y, one);
#else
        U2 A1 = tf_dev(ia1, ia1 + H_COORD, Kc, one);
        U2 A2 = tf_dev(ia2, ia2 + H_COORD, Kc, one);
        float lt1l = gumbel_lg2t(A1.x, one), lt1h = gumbel_lg2t(A1.y, one);
        float lt2l = gumbel_lg2t(A2.x, one), lt2h = gumbel_lg2t(A2.y, one);
#endif
        uint64_t ep1 = pk2(ex2a(fmaf(lt1l, -0.5f, f1l)), ex2a(fmaf(lt1h, -0.5f, f1h)));
        uint64_t ep2 = pk2(ex2a(fmaf(lt2l, -0.5f, f2l)), ex2a(fmaf(lt2h, -0.5f, f2h)));
        if (!v2) ep2 = 0;

        S2p = add2(S2p, ep1);
        gxp = fma2(ep1, g1xy.x, gxp);
        gyp = fma2(ep1, g1xy.y, gyp);
        gzp = fma2(ep1, g1zz, gzp);
        S2p = add2(S2p, ep2);
        gxp = fma2(ep2, g2xy.x, gxp);
        gyp = fma2(ep2, g2xy.y, gyp);
        gzp = fma2(ep2, g2zz, gzp);
    }

    float S2l, S2h, gxl, gxh, gyl, gyh, gzl, gzh;
    upk2(S2l, S2h, S2p);
    upk2(gxl, gxh, gxp);
    upk2(gyl, gyh, gyp);
    upk2(gzl, gzh, gzp);

    S2l = warp_sum(S2l); gxl = warp_sum(gxl); gyl = warp_sum(gyl); gzl = warp_sum(gzl);
    S2h = warp_sum(S2h); gxh = warp_sum(gxh); gyh = warp_sum(gyh); gzh = warp_sum(gzh);

    float kll = ccl + f0 + f2 + f4 - M1l + 6.907755278982137f;
    float klh = cch + f1 + f3 + f5 - M1h + 6.907755278982137f;

    float invl = 1.0f / S2l, invh = 1.0f / S2h;
    gxl *= invl; gyl *= invl; gzl *= invl;
    gxh *= invh; gyh *= invh; gzh *= invh;

    {
        float w00 = sm.Ws[lane * 3 + 0], w01 = sm.Ws[lane * 3 + 1], w02 = sm.Ws[lane * 3 + 2];
        float w10 = sm.Ws[(lane + 32) * 3 + 0], w11 = sm.Ws[(lane + 32) * 3 + 1], w12 = sm.Ws[(lane + 32) * 3 + 2];
        float b0 = sm.bs[lane], b1 = sm.bs[lane + 32];
        out[QCOFF + (size_t)rlo * 64 + lane]      = fmaf(w00, gxl, fmaf(w01, gyl, fmaf(w02, gzl, b0)));
        out[QCOFF + (size_t)rlo * 64 + 32 + lane] = fmaf(w10, gxl, fmaf(w11, gyl, fmaf(w12, gzl, b1)));
        out[QCOFF + (size_t)rhi * 64 + lane]      = fmaf(w00, gxh, fmaf(w01, gyh, fmaf(w02, gzh, b0)));
        out[QCOFF + (size_t)rhi * 64 + 32 + lane] = fmaf(w10, gxh, fmaf(w11, gyh, fmaf(w12, gzh, b1)));
    }
    return kll + klh;
}

// =======================================================================
// One per-codebook row-pair per warp (~7% of the work). Barrier-free.
// =======================================================================
__device__ __forceinline__ float code_pair(
    const CodeSm& sm, int rlo,
    const float* __restrict__ inputs, float* __restrict__ out,
    const TFK Kp, uint32_t one)
{
    const int lane = threadIdx.x & 31;
    const int rhi = rlo + HROWS;

    float in0l = inputs[(size_t)rlo * 64 + lane];
    float in1l = inputs[(size_t)rlo * 64 + 32 + lane];
    float in0h = inputs[(size_t)rhi * 64 + lane];
    float in1h = inputs[(size_t)rhi * 64 + 32 + lane];

    float hl0 = 0.f, hl1 = 0.f, hh0 = 0.f, hh1 = 0.f;
    const float2* lwt2 = reinterpret_cast<const float2*>(sm.lwt);
    #pragma unroll 8
    for (int d = 0; d < 32; d++) {
        float xl = __shfl_sync(0xffffffffu, in0l, d);
        float xh = __shfl_sync(0xffffffffu, in0h, d);
        float2 wv = lwt2[d * 32 + lane];
        hl0 = fmaf(xl, wv.x, hl0); hl1 = fmaf(xl, wv.y, hl1);
        hh0 = fmaf(xh, wv.x, hh0); hh1 = fmaf(xh, wv.y, hh1);
    }
    #pragma unroll 8
    for (int d = 0; d < 32; d++) {
        float xl = __shfl_sync(0xffffffffu, in1l, d);
        float xh = __shfl_sync(0xffffffffu, in1h, d);
        float2 wv = lwt2[(d + 32) * 32 + lane];
        hl0 = fmaf(xl, wv.x, hl0); hl1 = fmaf(xl, wv.y, hl1);
        hh0 = fmaf(xh, wv.x, hh0); hh1 = fmaf(xh, wv.y, hh1);
    }

    const int kk = lane >> 3;
    float xpl = 0.f, xph = 0.f;
    #pragma unroll
    for (int e2 = 0; e2 < 8; e2++) {
        int src = kk * 8 + e2;
        float a0l = __shfl_sync(0xffffffffu, hl0, src);
        float a1l = __shfl_sync(0xffffffffu, hl1, src);
        float a0h = __shfl_sync(0xffffffffu, hh0, src);
        float a1h = __shfl_sync(0xffffffffu, hh1, src);
        float ev0 = sm.emb_s[lane * 17 + 2 * e2];
        float ev1 = sm.emb_s[lane * 17 + 2 * e2 + 1];
        xpl = fmaf(a0l, ev0, fmaf(a1l, ev1, xpl));
        xph = fmaf(a0h, ev0, fmaf(a1h, ev1, xph));
    }

    float ml = grp8_max(xpl), mh = grp8_max(xph);
    float el = ex2a((xpl - ml) * 1.4426950408889634f);
    float eh = ex2a((xph - mh) * 1.4426950408889634f);
    float sl = grp8_sum(el), sh2 = grp8_sum(eh);
    float lzl = fmaf(0.6931471805599453f, lg2a(sl), ml);
    float lzh = fmaf(0.6931471805599453f, lg2a(sh2), mh);
    float lpl = xpl - lzl, lph = xph - lzh;
    float kl_l = grp8_sum(el * (lpl + 2.0794415416798357f)) / sl;
    float kl_h = grp8_sum(eh * (lph + 2.0794415416798357f)) / sh2;

    uint32_t idx = (uint32_t)rlo * 32u + (uint32_t)lane;
    float gl, gh;
#if RNG_PARTITIONABLE
    U2 A = tf_dev0(idx, Kp, one);
    U2 B = tf_dev0(idx + H_CODE, Kp, one);
    gl = bits_to_gumbel(A.x ^ A.y, one);
    gh = bits_to_gumbel(B.x ^ B.y, one);
#else
    U2 A = tf_dev(idx, idx + H_CODE, Kp, one);
    gl = bits_to_gumbel(A.x, one);
    gh = bits_to_gumbel(A.y, one);
#endif

    float zl = (lpl + gl) * 0.5f, zh = (lph + gh) * 0.5f;
    float m2l = grp8_max(zl), m2h = grp8_max(zh);
    float e2l = ex2a((zl - m2l) * 1.4426950408889634f);
    float e2h = ex2a((zh - m2h) * 1.4426950408889634f);
    float s2l = grp8_sum(e2l), s2h = grp8_sum(e2h);
    float ipl = e2l / s2l, iph = e2h / s2h;

    const int k2 = lane >> 3;
    const int e0 = (2 * lane) & 15;
    float ql0 = 0.f, ql1 = 0.f, qh0 = 0.f, qh1 = 0.f;
    #pragma unroll
    for (int nn = 0; nn < 8; nn++) {
        int src = k2 * 8 + nn;
        float wl = __shfl_sync(0xffffffffu, ipl, src);
        float wh = __shfl_sync(0xffffffffu, iph, src);
        float ev0 = sm.emb_s[src * 17 + e0];
        float ev1 = sm.emb_s[src * 17 + e0 + 1];
        ql0 = fmaf(wl, ev0, ql0); ql1 = fmaf(wl, ev1, ql1);
        qh0 = fmaf(wh, ev0, qh0); qh1 = fmaf(wh, ev1, qh1);
    }
    float2* o2 = reinterpret_cast<float2*>(out);
    o2[(size_t)rlo * 32 + lane] = make_float2(ql0, ql1);
    o2[(size_t)rhi * 32 + lane] = make_float2(qh0, qh1);

    float klrow = ((lane & 7) == 0) ? (kl_l + kl_h) : 0.0f;
    return warp_sum(klrow);
}

// Persistent, warp-independent fused kernel (R12 structure). After the
// one-time smem init (read-only thereafter) there are NO block barriers.
__global__ void __launch_bounds__(256, 4)
k_fused(const float* __restrict__ inputs, const float* __restrict__ linear_w,
        const float* __restrict__ linear_b, const float* __restrict__ emb,
        const float* __restrict__ lin_ws, float* __restrict__ out,
        TFK Kc, TFK Kp, uint32_t one, int loss_idx)
{
    __shared__ CoordSm smc;
    __shared__ CodeSm smq;
    __shared__ int is_last;
    const int tid = threadIdx.x;

    // one-time smem setup for BOTH work types
    for (int i = tid; i < 192; i += 256) smc.Ws[i] = linear_w[i];
    for (int i = tid; i < 64;  i += 256) smc.bs[i] = linear_b[i];
    for (int n = tid; n < NC; n += 256) {
        int i10 = n / 100, j10 = (n / 10) % 10, k10 = n % 10;
        // meshgrid 'xy': g[n] = (x[j], x[i], x[k]); stored duplicated for f32x2
        float gx = (float)(j10 * (1.5 / 9.0));
        float gy = (float)(i10 * (1.5 / 9.0));
        float gz = (float)(k10 * (1.5 / 9.0));
        smc.gA[n] = make_ulonglong2(pk2(gx, gx), pk2(gy, gy));
        smc.gB[n] = pk2(gz, gz);
    }
    for (int i = tid; i < 4096; i += 256) {
        int ke = i >> 6, d = i & 63;
        smq.lwt[d * 64 + ke] = lin_ws[i];
    }
    for (int i = tid; i < 512; i += 256)
        smq.emb_s[(i >> 4) * 17 + (i & 15)] = emb[i];
    __syncthreads();   // the ONLY block barrier before the final reduction

    const int gw = blockIdx.x * 8 + (tid >> 5);   // global warp id
    double klacc = 0.0;

    // coord row-pairs: rlo in [0, HROWS), strided by NWARP
    for (int rlo = gw; rlo < HROWS; rlo += NWARP)
        klacc += (double)coord_pair(smc, rlo, inputs, out, Kc, one);

    // code row-pairs
    for (int rlo = gw; rlo < HROWS; rlo += NWARP)
        klacc += (double)code_pair(smq, rlo, inputs, out, Kp, one);

    if ((tid & 31) == 0) g_parts[gw] = klacc;

    __threadfence();
    __syncthreads();
    if (tid == 0) {
        unsigned int prev = atomicAdd(&g_done, 1u);
        is_last = (prev == gridDim.x - 1u);
    }
    __syncthreads();
    if (is_last) {
        double* red = reinterpret_cast<double*>(&smc);   // reuse smem
        double s = 0;
        for (int i = tid; i < NWARP; i += 256) s += g_parts[i];
        red[tid] = s;
        __syncthreads();
        #pragma unroll
        for (int o = 128; o; o >>= 1) {
            if (tid < o) red[tid] += red[tid + o];
            __syncthreads();
        }
        if (tid == 0) {
            out[loss_idx] = (float)(red[0] / 5.0);
            g_done = 0;   // reset for next graph replay
        }
    }
}

extern "C" void kernel_launch(void* const* d_in, const int* in_sizes, int n_in,
                              void* d_out, int out_size) {
    const float* inputs   = (const float*)d_in[0];
    const float* linear_w = (const float*)d_in[1];
    const float* linear_b = (const float*)d_in[2];
    const float* emb      = (const float*)d_in[3];
    const float* lin_ws   = (const float*)d_in[4];
    float* out = (float*)d_out;

    // kc, kp = jax.random.split(jax.random.key(42))
#if RNG_PARTITIONABLE
    U2 a = tf_host(0u, 42u, 0u, 0u);
    U2 b = tf_host(0u, 42u, 0u, 1u);
    uint32_t kc0 = a.x, kc1 = a.y;
    uint32_t kp0 = b.x, kp1 = b.y;
#else
    U2 a = tf_host(0u, 42u, 0u, 2u);
    U2 b = tf_host(0u, 42u, 1u, 3u);
    uint32_t kc0 = a.x, kc1 = b.x;
    uint32_t kp0 = a.y, kp1 = b.y;
#endif
    TFK Kc = make_tfk(kc0, kc1);
    TFK Kp = make_tfk(kp0, kp1);

    k_fused<<<NBLK, 256>>>(inputs, linear_w, linear_b, emb, lin_ws, out,
                           Kc, Kp, 1u, out_size - 1);
}

// round 16
// speedup vs baseline: 1.0087x; 1.0087x over previous
#include <cuda_runtime.h>
#include <cstdint>

// jax threefry mode: 1 = threefry_partitionable (jax >= 0.5.0 default), 0 = legacy
#ifndef RNG_PARTITIONABLE
#define RNG_PARTITIONABLE 1
#endif

#define HROWS  32768
#define NC     1000
#define H_COORD 32768000u   // half of 32*2048*1000
#define H_CODE  1048576u    // half of 32*2048*32
#define QCOFF  4194304      // 65536*64
#define NBLK   592          // 4 blocks/SM on 148 SMs: all co-resident
#define NWARP  (NBLK * 8)   // 4736 independent warps

__device__ double g_parts[NWARP];
__device__ unsigned int g_done;   // zero-init; reset by last block each run

// ---------------- threefry2x32 (matches jax) ----------------
__host__ __device__ __forceinline__ uint32_t rotl32(uint32_t x, int r) {
#ifdef __CUDA_ARCH__
    return __funnelshift_l(x, x, r);
#else
    return (x << r) | (x >> (32 - r));
#endif
}

struct U2 { uint32_t x, y; };

// Key-injection schedule: after round-group j, x0 += A[j], x1 += B[j].
struct TFK {
    uint32_t a0, b0, a1, b1, a2, b2, a3, b3, a4, b4, a5, b5;
};

__host__ inline TFK make_tfk(uint32_t k0, uint32_t k1) {
    uint32_t k2 = k0 ^ k1 ^ 0x1BD11BDAu;
    TFK K;
    K.a0 = k0; K.b0 = k1;
    K.a1 = k1; K.b1 = k2 + 1u;
    K.a2 = k2; K.b2 = k0 + 2u;
    K.a3 = k0; K.b3 = k1 + 3u;
    K.a4 = k1; K.b4 = k2 + 4u;
    K.a5 = k2; K.b5 = k0 + 5u;
    return K;
}

__host__ inline U2 tf_host(uint32_t k0, uint32_t k1, uint32_t x0, uint32_t x1) {
    uint32_t k2 = k0 ^ k1 ^ 0x1BD11BDAu;
    x0 += k0; x1 += k1;
#define TFR(r) { x0 += x1; x1 = rotl32(x1, r); x1 ^= x0; }
    TFR(13) TFR(15) TFR(26) TFR(6)
    x0 += k1; x1 += k2 + 1u;
    TFR(17) TFR(29) TFR(16) TFR(24)
    x0 += k2; x1 += k0 + 2u;
    TFR(13) TFR(15) TFR(26) TFR(6)
    x0 += k0; x1 += k1 + 3u;
    TFR(17) TFR(29) TFR(16) TFR(24)
    x0 += k1; x1 += k2 + 4u;
    TFR(13) TFR(15) TFR(26) TFR(6)
    x0 += k2; x1 += k0 + 5u;
#undef TFR
    U2 r; r.x = x0; r.y = x1; return r;
}

// Integer add on the FMA pipe: IMAD r = a*one + b, `one` is an opaque runtime 1.
__device__ __forceinline__ uint32_t addi(uint32_t a, uint32_t b, uint32_t one) {
    uint32_t r;
    asm("mad.lo.u32 %0, %1, %2, %3;" : "=r"(r) : "r"(a), "r"(one), "r"(b));
    return r;
}

// Cipher specialized for x0-start == 0 (partitionable counters). ALL adds
// (round adds + both key injections) go through IMAD (fma pipe); SHF/LOP3
// stay on alu. (Exact R12 schedule — locally optimal per R5/R11/R14/R15.)
__device__ __forceinline__ U2 tf_dev0(uint32_t x1, const TFK K, uint32_t one) {
    uint32_t x0 = K.a0;
    x1 = addi(x1, K.b0, one);
#define TFRD(r) { x0 = addi(x0, x1, one); x1 = rotl32(x1, r) ^ x0; }
    TFRD(13) TFRD(15) TFRD(26) TFRD(6)
    x0 = addi(x0, K.a1, one); x1 = addi(x1, K.b1, one);
    TFRD(17) TFRD(29) TFRD(16) TFRD(24)
    x0 = addi(x0, K.a2, one); x1 = addi(x1, K.b2, one);
    TFRD(13) TFRD(15) TFRD(26) TFRD(6)
    x0 = addi(x0, K.a3, one); x1 = addi(x1, K.b3, one);
    TFRD(17) TFRD(29) TFRD(16) TFRD(24)
    x0 = addi(x0, K.a4, one); x1 = addi(x1, K.b4, one);
    TFRD(13) TFRD(15) TFRD(26) TFRD(6)
    x0 = addi(x0, K.a5, one); x1 = addi(x1, K.b5, one);
#undef TFRD
    U2 r; r.x = x0; r.y = x1; return r;
}

// general device cipher (legacy path)
__device__ __forceinline__ U2 tf_dev(uint32_t x0, uint32_t x1, const TFK K, uint32_t one) {
#define TFRD(r) { x0 = addi(x0, x1, one); x1 = rotl32(x1, r) ^ x0; }
    x0 = addi(x0, K.a0, one); x1 = addi(x1, K.b0, one);
    TFRD(13) TFRD(15) TFRD(26) TFRD(6)
    x0 = addi(x0, K.a1, one); x1 = addi(x1, K.b1, one);
    TFRD(17) TFRD(29) TFRD(16) TFRD(24)
    x0 = addi(x0, K.a2, one); x1 = addi(x1, K.b2, one);
    TFRD(13) TFRD(15) TFRD(26) TFRD(6)
    x0 = addi(x0, K.a3, one); x1 = addi(x1, K.b3, one);
    TFRD(17) TFRD(29) TFRD(16) TFRD(24)
    x0 = addi(x0, K.a4, one); x1 = addi(x1, K.b4, one);
    TFRD(13) TFRD(15) TFRD(26) TFRD(6)
    x0 = addi(x0, K.a5, one); x1 = addi(x1, K.b5, one);
#undef TFRD
    U2 r; r.x = x0; r.y = x1; return r;
}

__device__ __forceinline__ float ex2a(float x) {
    float r; asm("ex2.approx.ftz.f32 %0, %1;" : "=f"(r) : "f"(x)); return r;
}
__device__ __forceinline__ float lg2a(float x) {
    float r; asm("lg2.approx.ftz.f32 %0, %1;" : "=f"(r) : "f"(x)); return r;
}

// Returns lg2(t), t = 1e-20 - ln(u + 1e-20); gumbel g = -ln2 * lg2(t).
// eps folded into the FMA constant (u + 1e-20 == u in fp32 for nonzero u).
// Poly branch keeps relative accuracy near u==1 where MUFU abs error blows up.
__device__ __forceinline__ float gumbel_lg2t(uint32_t bits, uint32_t one) {
    uint32_t hi = __umulhi(bits, 0x00800000u);           // bits >> 9
    float u = __uint_as_float(addi(hi, 0x3f800000u, one)) - 1.0f;
    float d = 1.0f - u;                        // exact (Sterbenz) for u >= 0.5
    float series = fmaf(d, fmaf(d, fmaf(d, 0.25f, 0.33333334f), 0.5f), 1.0f);
    float t_poly = fmaf(d, series, 1e-20f);    // 1e-20 - ln(1-d), |d|<=1/16
    float t_lf = fmaf(-0.6931471805599453f, lg2a(u), 1e-20f);
    float t = (d <= 0.0625f) ? t_poly : t_lf;  // > 0
    return lg2a(t);
}

__device__ __forceinline__ float bits_to_gumbel(uint32_t bits, uint32_t one) {
    return -0.6931471805599453f * gumbel_lg2t(bits, one);
}

__device__ __forceinline__ float warp_sum(float v) {
    #pragma unroll
    for (int o = 16; o; o >>= 1) v += __shfl_xor_sync(0xffffffffu, v, o);
    return v;
}
__device__ __forceinline__ float grp8_max(float v) {
    v = fmaxf(v, __shfl_xor_sync(0xffffffffu, v, 4));
    v = fmaxf(v, __shfl_xor_sync(0xffffffffu, v, 2));
    v = fmaxf(v, __shfl_xor_sync(0xffffffffu, v, 1));
    return v;
}
__device__ __forceinline__ float grp8_sum(float v) {
    v += __shfl_xor_sync(0xffffffffu, v, 4);
    v += __shfl_xor_sync(0xffffffffu, v, 2);
    v += __shfl_xor_sync(0xffffffffu, v, 1);
    return v;
}

// ---------------- shared-memory (read-only after init) ----------------
struct CoordSm {
    float4 grid[NC];     // 16000 B
    float  Ws[192];
    float  bs[64];
};
struct CodeSm {
    float  lwt[4096];       // 16384 B  [d][ke] transposed lin_ws
    float  emb_s[32 * 17];  //  2176 B
};

// =======================================================================
// One coordinate row-pair per warp. ILP x4 cipher chains; factorized
// first-softmax KL via shuffles; barrier-free. Returns kll+klh.
// =======================================================================
__device__ __forceinline__ float coord_pair(
    const CoordSm& sm, int rlo,
    const float* __restrict__ inputs, float* __restrict__ out,
    const TFK Kc, uint32_t one)
{
    const int lane = threadIdx.x & 31;
    const int rhi = rlo + HROWS;

    float p0l, p1l, p2l, ccl, p0h, p1h, p2h, cch;
    {
        float il0 = inputs[(size_t)rlo * 64 + lane];
        float il1 = inputs[(size_t)rlo * 64 + 32 + lane];
        float ih0 = inputs[(size_t)rhi * 64 + lane];
        float ih1 = inputs[(size_t)rhi * 64 + 32 + lane];
        float w00 = sm.Ws[lane * 3 + 0], w01 = sm.Ws[lane * 3 + 1], w02 = sm.Ws[lane * 3 + 2];
        float w10 = sm.Ws[(lane + 32) * 3 + 0], w11 = sm.Ws[(lane + 32) * 3 + 1], w12 = sm.Ws[(lane + 32) * 3 + 2];
        float b0 = sm.bs[lane], b1 = sm.bs[lane + 32];

        p0l = warp_sum(fmaf(il0, w00, il1 * w10));
        p1l = warp_sum(fmaf(il0, w01, il1 * w11));
        p2l = warp_sum(fmaf(il0, w02, il1 * w12));
        ccl = warp_sum(fmaf(il0, b0,  il1 * b1));
        p0h = warp_sum(fmaf(ih0, w00, ih1 * w10));
        p1h = warp_sum(fmaf(ih0, w01, ih1 * w11));
        p2h = warp_sum(fmaf(ih0, w02, ih1 * w12));
        cch = warp_sum(fmaf(ih0, b0,  ih1 * b1));
    }

    const float L2E  = 1.4426950408889634f;
    const float HL2E = 0.7213475204444817f;
    const float LN2  = 0.6931471805599453f;
    float M1l = ccl + 1.5f * (fmaxf(p0l, 0.f) + fmaxf(p1l, 0.f) + fmaxf(p2l, 0.f));
    float M1h = cch + 1.5f * (fmaxf(p0h, 0.f) + fmaxf(p1h, 0.f) + fmaxf(p2h, 0.f));

    // fully pre-scaled exponent: e2 = exp2(ps.g + cB - lt/2)
    float ps0l = p0l * HL2E, ps1l = p1l * HL2E, ps2l = p2l * HL2E;
    float ps0h = p0h * HL2E, ps1h = p1h * HL2E, ps2h = p2h * HL2E;
    float cBl = (ccl - M1l - 16.0f) * HL2E;
    float cBh = (cch - M1h - 16.0f) * HL2E;

    // ---- factorized logZ/KL: lanes 0..5 each handle one (row,dim);
    // shared afterwards by shuffles (no smem, no barrier) ----
    float fv = 0.0f;
    {
        int dim = lane >> 1;
        bool hiRow = lane & 1;
        float p = dim == 0 ? (hiRow ? p0h : p0l)
                : dim == 1 ? (hiRow ? p1h : p1l)
                           : (hiRow ? p2h : p2l);
        if (lane < 6) {
            float mx = 1.5f * fmaxf(p, 0.f);
            float P = 0.f, X = 0.f;
            #pragma unroll
            for (int t = 0; t < 10; t++) {
                float xs = (float)t * (float)(1.5 / 9.0);
                float e = ex2a((p * xs - mx) * L2E);
                P += e; X = fmaf(xs, e, X);
            }
            fv = p * (X / P) - LN2 * lg2a(P);   // E_dim - lnP_dim
        }
    }
    float f0 = __shfl_sync(0xffffffffu, fv, 0);
    float f1 = __shfl_sync(0xffffffffu, fv, 1);
    float f2 = __shfl_sync(0xffffffffu, fv, 2);
    float f3 = __shfl_sync(0xffffffffu, fv, 3);
    float f4 = __shfl_sync(0xffffffffu, fv, 4);
    float f5 = __shfl_sync(0xffffffffu, fv, 5);

    float S2l = 0.f, gxl = 0.f, gyl = 0.f, gzl = 0.f;
    float S2h = 0.f, gxh = 0.f, gyh = 0.f, gzh = 0.f;

    uint32_t ia1 = (uint32_t)rlo * 1000u + (uint32_t)lane;
    uint32_t ia2 = ia1 + 32u;
#if RNG_PARTITIONABLE
    uint32_t ib1 = ia1 + H_COORD;
    uint32_t ib2 = ib1 + 32u;
#endif

    // ---- 15 full iterations (unroll 3: window for cross-iteration
    // scheduling of the cipher chains; only change vs the R12 champion) ----
    #pragma unroll 3
    for (int t = 0; t < 15; t++) {
        const int n  = lane + (t << 6);
        float4 g1 = sm.grid[n];
        float4 g2 = sm.grid[n + 32];

        float f1l = fmaf(ps0l, g1.x, fmaf(ps1l, g1.y, fmaf(ps2l, g1.z, cBl)));
        float f1h = fmaf(ps0h, g1.x, fmaf(ps1h, g1.y, fmaf(ps2h, g1.z, cBh)));
        float f2l = fmaf(ps0l, g2.x, fmaf(ps1l, g2.y, fmaf(ps2l, g2.z, cBl)));
        float f2h = fmaf(ps0h, g2.x, fmaf(ps1h, g2.y, fmaf(ps2h, g2.z, cBh)));

#if RNG_PARTITIONABLE
        U2 A1 = tf_dev0(ia1, Kc, one);
        U2 A2 = tf_dev0(ia2, Kc, one);
        U2 B1 = tf_dev0(ib1, Kc, one);
        U2 B2 = tf_dev0(ib2, Kc, one);
        float lt1l = gumbel_lg2t(A1.x ^ A1.y, one);
        float lt2l = gumbel_lg2t(A2.x ^ A2.y, one);
        float lt1h = gumbel_lg2t(B1.x ^ B1.y, one);
        float lt2h = gumbel_lg2t(B2.x ^ B2.y, one);
        ia1 = addi(ia1, 64u, one); ia2 = addi(ia2, 64u, one);
        ib1 = addi(ib1, 64u, one); ib2 = addi(ib2, 64u, one);
#else
        U2 A1 = tf_dev(ia1, ia1 + H_COORD, Kc, one);
        U2 A2 = tf_dev(ia2, ia2 + H_COORD, Kc, one);
        float lt1l = gumbel_lg2t(A1.x, one), lt1h = gumbel_lg2t(A1.y, one);
        float lt2l = gumbel_lg2t(A2.x, one), lt2h = gumbel_lg2t(A2.y, one);
        ia1 = addi(ia1, 64u, one); ia2 = addi(ia2, 64u, one);
#endif
        float e1l = ex2a(fmaf(lt1l, -0.5f, f1l));
        float e1h = ex2a(fmaf(lt1h, -0.5f, f1h));
        float e2l = ex2a(fmaf(lt2l, -0.5f, f2l));
        float e2h = ex2a(fmaf(lt2h, -0.5f, f2h));

        S2l += e1l; gxl = fmaf(e1l, g1.x, gxl); gyl = fmaf(e1l, g1.y, gyl); gzl = fmaf(e1l, g1.z, gzl);
        S2h += e1h; gxh = fmaf(e1h, g1.x, gxh); gyh = fmaf(e1h, g1.y, gyh); gzh = fmaf(e1h, g1.z, gzh);
        S2l += e2l; gxl = fmaf(e2l, g2.x, gxl); gyl = fmaf(e2l, g2.y, gyl); gzl = fmaf(e2l, g2.z, gzl);
        S2h += e2h; gxh = fmaf(e2h, g2.x, gxh); gyh = fmaf(e2h, g2.y, gyh); gzh = fmaf(e2h, g2.z, gzh);
    }

    // ---- tail: n in [960,1000): point1 always valid, point2 iff lane<8 ----
    {
        const int n = lane + 960;
        const bool v2 = (lane < 8);
        float4 g1 = sm.grid[n];
        float4 g2 = sm.grid[v2 ? (n + 32) : n];

        float f1l = fmaf(ps0l, g1.x, fmaf(ps1l, g1.y, fmaf(ps2l, g1.z, cBl)));
        float f1h = fmaf(ps0h, g1.x, fmaf(ps1h, g1.y, fmaf(ps2h, g1.z, cBh)));
        float f2l = fmaf(ps0l, g2.x, fmaf(ps1l, g2.y, fmaf(ps2l, g2.z, cBl)));
        float f2h = fmaf(ps0h, g2.x, fmaf(ps1h, g2.y, fmaf(ps2h, g2.z, cBh)));

#if RNG_PARTITIONABLE
        U2 A1 = tf_dev0(ia1, Kc, one);
        U2 A2 = tf_dev0(ia2, Kc, one);
        U2 B1 = tf_dev0(ib1, Kc, one);
        U2 B2 = tf_dev0(ib2, Kc, one);
        float lt1l = gumbel_lg2t(A1.x ^ A1.y, one);
        float lt2l = gumbel_lg2t(A2.x ^ A2.y, one);
        float lt1h = gumbel_lg2t(B1.x ^ B1.y, one);
        float lt2h = gumbel_lg2t(B2.x ^ B2.y, one);
#else
        U2 A1 = tf_dev(ia1, ia1 + H_COORD, Kc, one);
        U2 A2 = tf_dev(ia2, ia2 + H_COORD, Kc, one);
        float lt1l = gumbel_lg2t(A1.x, one), lt1h = gumbel_lg2t(A1.y, one);
        float lt2l = gumbel_lg2t(A2.x, one), lt2h = gumbel_lg2t(A2.y, one);
#endif
        float e1l = ex2a(fmaf(lt1l, -0.5f, f1l));
        float e1h = ex2a(fmaf(lt1h, -0.5f, f1h));
        float e2l = ex2a(fmaf(lt2l, -0.5f, f2l));
        float e2h = ex2a(fmaf(lt2h, -0.5f, f2h));
        if (!v2) { e2l = 0.f; e2h = 0.f; }

        S2l += e1l; gxl = fmaf(e1l, g1.x, gxl); gyl = fmaf(e1l, g1.y, gyl); gzl = fmaf(e1l, g1.z, gzl);
        S2h += e1h; gxh = fmaf(e1h, g1.x, gxh); gyh = fmaf(e1h, g1.y, gyh); gzh = fmaf(e1h, g1.z, gzh);
        S2l += e2l; gxl = fmaf(e2l, g2.x, gxl); gyl = fmaf(e2l, g2.y, gyl); gzl = fmaf(e2l, g2.z, gzl);
        S2h += e2h; gxh = fmaf(e2h, g2.x, gxh); gyh = fmaf(e2h, g2.y, gyh); gzh = fmaf(e2h, g2.z, gzh);
    }

    S2l = warp_sum(S2l); gxl = warp_sum(gxl); gyl = warp_sum(gyl); gzl = warp_sum(gzl);
    S2h = warp_sum(S2h); gxh = warp_sum(gxh); gyh = warp_sum(gyh); gzh = warp_sum(gzh);

    float kll = ccl + f0 + f2 + f4 - M1l + 6.907755278982137f;
    float klh = cch + f1 + f3 + f5 - M1h + 6.907755278982137f;

    float invl = 1.0f / S2l, invh = 1.0f / S2h;
    gxl *= invl; gyl *= invl; gzl *= invl;
    gxh *= invh; gyh *= invh; gzh *= invh;

    {
        float w00 = sm.Ws[lane * 3 + 0], w01 = sm.Ws[lane * 3 + 1], w02 = sm.Ws[lane * 3 + 2];
        float w10 = sm.Ws[(lane + 32) * 3 + 0], w11 = sm.Ws[(lane + 32) * 3 + 1], w12 = sm.Ws[(lane + 32) * 3 + 2];
        float b0 = sm.bs[lane], b1 = sm.bs[lane + 32];
        out[QCOFF + (size_t)rlo * 64 + lane]      = fmaf(w00, gxl, fmaf(w01, gyl, fmaf(w02, gzl, b0)));
        out[QCOFF + (size_t)rlo * 64 + 32 + lane] = fmaf(w10, gxl, fmaf(w11, gyl, fmaf(w12, gzl, b1)));
        out[QCOFF + (size_t)rhi * 64 + lane]      = fmaf(w00, gxh, fmaf(w01, gyh, fmaf(w02, gzh, b0)));
        out[QCOFF + (size_t)rhi * 64 + 32 + lane] = fmaf(w10, gxh, fmaf(w11, gyh, fmaf(w12, gzh, b1)));
    }
    return kll + klh;
}

// =======================================================================
// One per-codebook row-pair per warp (~7% of the work). Barrier-free.
// =======================================================================
__device__ __forceinline__ float code_pair(
    const CodeSm& sm, int rlo,
    const float* __restrict__ inputs, float* __restrict__ out,
    const TFK Kp, uint32_t one)
{
    const int lane = threadIdx.x & 31;
    const int rhi = rlo + HROWS;

    float in0l = inputs[(size_t)rlo * 64 + lane];
    float in1l = inputs[(size_t)rlo * 64 + 32 + lane];
    float in0h = inputs[(size_t)rhi * 64 + lane];
    float in1h = inputs[(size_t)rhi * 64 + 32 + lane];

    float hl0 = 0.f, hl1 = 0.f, hh0 = 0.f, hh1 = 0.f;
    const float2* lwt2 = reinterpret_cast<const float2*>(sm.lwt);
    #pragma unroll 8
    for (int d = 0; d < 32; d++) {
        float xl = __shfl_sync(0xffffffffu, in0l, d);
        float xh = __shfl_sync(0xffffffffu, in0h, d);
        float2 wv = lwt2[d * 32 + lane];
        hl0 = fmaf(xl, wv.x, hl0); hl1 = fmaf(xl, wv.y, hl1);
        hh0 = fmaf(xh, wv.x, hh0); hh1 = fmaf(xh, wv.y, hh1);
    }
    #pragma unroll 8
    for (int d = 0; d < 32; d++) {
        float xl = __shfl_sync(0xffffffffu, in1l, d);
        float xh = __shfl_sync(0xffffffffu, in1h, d);
        float2 wv = lwt2[(d + 32) * 32 + lane];
        hl0 = fmaf(xl, wv.x, hl0); hl1 = fmaf(xl, wv.y, hl1);
        hh0 = fmaf(xh, wv.x, hh0); hh1 = fmaf(xh, wv.y, hh1);
    }

    const int kk = lane >> 3;
    float xpl = 0.f, xph = 0.f;
    #pragma unroll
    for (int e2 = 0; e2 < 8; e2++) {
        int src = kk * 8 + e2;
        float a0l = __shfl_sync(0xffffffffu, hl0, src);
        float a1l = __shfl_sync(0xffffffffu, hl1, src);
        float a0h = __shfl_sync(0xffffffffu, hh0, src);
        float a1h = __shfl_sync(0xffffffffu, hh1, src);
        float ev0 = sm.emb_s[lane * 17 + 2 * e2];
        float ev1 = sm.emb_s[lane * 17 + 2 * e2 + 1];
        xpl = fmaf(a0l, ev0, fmaf(a1l, ev1, xpl));
        xph = fmaf(a0h, ev0, fmaf(a1h, ev1, xph));
    }

    float ml = grp8_max(xpl), mh = grp8_max(xph);
    float el = ex2a((xpl - ml) * 1.4426950408889634f);
    float eh = ex2a((xph - mh) * 1.4426950408889634f);
    float sl = grp8_sum(el), sh2 = grp8_sum(eh);
    float lzl = fmaf(0.6931471805599453f, lg2a(sl), ml);
    float lzh = fmaf(0.6931471805599453f, lg2a(sh2), mh);
    float lpl = xpl - lzl, lph = xph - lzh;
    float kl_l = grp8_sum(el * (lpl + 2.0794415416798357f)) / sl;
    float kl_h = grp8_sum(eh * (lph + 2.0794415416798357f)) / sh2;

    uint32_t idx = (uint32_t)rlo * 32u + (uint32_t)lane;
    float gl, gh;
#if RNG_PARTITIONABLE
    U2 A = tf_dev0(idx, Kp, one);
    U2 B = tf_dev0(idx + H_CODE, Kp, one);
    gl = bits_to_gumbel(A.x ^ A.y, one);
    gh = bits_to_gumbel(B.x ^ B.y, one);
#else
    U2 A = tf_dev(idx, idx + H_CODE, Kp, one);
    gl = bits_to_gumbel(A.x, one);
    gh = bits_to_gumbel(A.y, one);
#endif

    float zl = (lpl + gl) * 0.5f, zh = (lph + gh) * 0.5f;
    float m2l = grp8_max(zl), m2h = grp8_max(zh);
    float e2l = ex2a((zl - m2l) * 1.4426950408889634f);
    float e2h = ex2a((zh - m2h) * 1.4426950408889634f);
    float s2l = grp8_sum(e2l), s2h = grp8_sum(e2h);
    float ipl = e2l / s2l, iph = e2h / s2h;

    const int k2 = lane >> 3;
    const int e0 = (2 * lane) & 15;
    float ql0 = 0.f, ql1 = 0.f, qh0 = 0.f, qh1 = 0.f;
    #pragma unroll
    for (int nn = 0; nn < 8; nn++) {
        int src = k2 * 8 + nn;
        float wl = __shfl_sync(0xffffffffu, ipl, src);
        float wh = __shfl_sync(0xffffffffu, iph, src);
        float ev0 = sm.emb_s[src * 17 + e0];
        float ev1 = sm.emb_s[src * 17 + e0 + 1];
        ql0 = fmaf(wl, ev0, ql0); ql1 = fmaf(wl, ev1, ql1);
        qh0 = fmaf(wh, ev0, qh0); qh1 = fmaf(wh, ev1, qh1);
    }
    float2* o2 = reinterpret_cast<float2*>(out);
    o2[(size_t)rlo * 32 + lane] = make_float2(ql0, ql1);
    o2[(size_t)rhi * 32 + lane] = make_float2(qh0, qh1);

    float klrow = ((lane & 7) == 0) ? (kl_l + kl_h) : 0.0f;
    return warp_sum(klrow);
}

// Persistent, warp-independent fused kernel (R12 structure). After the
// one-time smem init (read-only thereafter) there are NO block barriers:
// each warp owns a static strided set of coord row-pairs then code
// row-pairs, accumulating its KL partial in a register double. Last block
// reduces the loss.
__global__ void __launch_bounds__(256, 4)
k_fused(const float* __restrict__ inputs, const float* __restrict__ linear_w,
        const float* __restrict__ linear_b, const float* __restrict__ emb,
        const float* __restrict__ lin_ws, float* __restrict__ out,
        TFK Kc, TFK Kp, uint32_t one, int loss_idx)
{
    __shared__ CoordSm smc;
    __shared__ CodeSm smq;
    __shared__ int is_last;
    const int tid = threadIdx.x;

    // one-time smem setup for BOTH work types
    for (int i = tid; i < 192; i += 256) smc.Ws[i] = linear_w[i];
    for (int i = tid; i < 64;  i += 256) smc.bs[i] = linear_b[i];
    for (int n = tid; n < NC; n += 256) {
        int i10 = n / 100, j10 = (n / 10) % 10, k10 = n % 10;
        // meshgrid 'xy': g[n] = (x[j], x[i], x[k])
        smc.grid[n] = make_float4((float)(j10 * (1.5 / 9.0)),
                                  (float)(i10 * (1.5 / 9.0)),
                                  (float)(k10 * (1.5 / 9.0)), 0.0f);
    }
    for (int i = tid; i < 4096; i += 256) {
        int ke = i >> 6, d = i & 63;
        smq.lwt[d * 64 + ke] = lin_ws[i];
    }
    for (int i = tid; i < 512; i += 256)
        smq.emb_s[(i >> 4) * 17 + (i & 15)] = emb[i];
    __syncthreads();   // the ONLY block barrier before the final reduction

    const int gw = blockIdx.x * 8 + (tid >> 5);   // global warp id
    double klacc = 0.0;

    // coord row-pairs: rlo in [0, HROWS), strided by NWARP
    for (int rlo = gw; rlo < HROWS; rlo += NWARP)
        klacc += (double)coord_pair(smc, rlo, inputs, out, Kc, one);

    // code row-pairs
    for (int rlo = gw; rlo < HROWS; rlo += NWARP)
        klacc += (double)code_pair(smq, rlo, inputs, out, Kp, one);

    if ((tid & 31) == 0) g_parts[gw] = klacc;

    __threadfence();
    __syncthreads();
    if (tid == 0) {
        unsigned int prev = atomicAdd(&g_done, 1u);
        is_last = (prev == gridDim.x - 1u);
    }
    __syncthreads();
    if (is_last) {
        double* red = reinterpret_cast<double*>(&smc);   // reuse smem
        double s = 0;
        for (int i = tid; i < NWARP; i += 256) s += g_parts[i];
        red[tid] = s;
        __syncthreads();
        #pragma unroll
        for (int o = 128; o; o >>= 1) {
            if (tid < o) red[tid] += red[tid + o];
            __syncthreads();
        }
        if (tid == 0) {
            out[loss_idx] = (float)(red[0] / 5.0);
            g_done = 0;   // reset for next graph replay
        }
    }
}

extern "C" void kernel_launch(void* const* d_in, const int* in_sizes, int n_in,
                              void* d_out, int out_size) {
    const float* inputs   = (const float*)d_in[0];
    const float* linear_w = (const float*)d_in[1];
    const float* linear_b = (const float*)d_in[2];
    const float* emb      = (const float*)d_in[3];
    const float* lin_ws   = (const float*)d_in[4];
    float* out = (float*)d_out;

    // kc, kp = jax.random.split(jax.random.key(42))
#if RNG_PARTITIONABLE
    U2 a = tf_host(0u, 42u, 0u, 0u);
    U2 b = tf_host(0u, 42u, 0u, 1u);
    uint32_t kc0 = a.x, kc1 = a.y;
    uint32_t kp0 = b.x, kp1 = b.y;
#else
    U2 a = tf_host(0u, 42u, 0u, 2u);
    U2 b = tf_host(0u, 42u, 1u, 3u);
    uint32_t kc0 = a.x, kc1 = b.x;
    uint32_t kp0 = a.y, kp1 = b.y;
#endif
    TFK Kc = make_tfk(kc0, kc1);
    TFK Kp = make_tfk(kp0, kp1);

    k_fused<<<NBLK, 256>>>(inputs, linear_w, linear_b, emb, lin_ws, out,
                           Kc, Kp, 1u, out_size - 1);
}

// round 17
// speedup vs baseline: 1.0373x; 1.0284x over previous
#include <cuda_runtime.h>
#include <cstdint>

// jax threefry mode: 1 = threefry_partitionable (jax >= 0.5.0 default), 0 = legacy
#ifndef RNG_PARTITIONABLE
#define RNG_PARTITIONABLE 1
#endif

#define HROWS  32768
#define NC     1000
#define H_COORD 32768000u   // half of 32*2048*1000
#define H_CODE  1048576u    // half of 32*2048*32
#define QCOFF  4194304      // 65536*64
#define NBLK   592          // 4 blocks/SM on 148 SMs: all co-resident
#define NWARP  (NBLK * 8)   // 4736 independent warps

__device__ double g_parts[NWARP];
__device__ unsigned int g_done;   // zero-init; reset by last block each run

// ---------------- threefry2x32 (matches jax) ----------------
__host__ __device__ __forceinline__ uint32_t rotl32(uint32_t x, int r) {
#ifdef __CUDA_ARCH__
    return __funnelshift_l(x, x, r);
#else
    return (x << r) | (x >> (32 - r));
#endif
}

struct U2 { uint32_t x, y; };

// Key-injection schedule: after round-group j, x0 += A[j], x1 += B[j].
struct TFK {
    uint32_t a0, b0, a1, b1, a2, b2, a3, b3, a4, b4, a5, b5;
};

__host__ inline TFK make_tfk(uint32_t k0, uint32_t k1) {
    uint32_t k2 = k0 ^ k1 ^ 0x1BD11BDAu;
    TFK K;
    K.a0 = k0; K.b0 = k1;
    K.a1 = k1; K.b1 = k2 + 1u;
    K.a2 = k2; K.b2 = k0 + 2u;
    K.a3 = k0; K.b3 = k1 + 3u;
    K.a4 = k1; K.b4 = k2 + 4u;
    K.a5 = k2; K.b5 = k0 + 5u;
    return K;
}

__host__ inline U2 tf_host(uint32_t k0, uint32_t k1, uint32_t x0, uint32_t x1) {
    uint32_t k2 = k0 ^ k1 ^ 0x1BD11BDAu;
    x0 += k0; x1 += k1;
#define TFR(r) { x0 += x1; x1 = rotl32(x1, r); x1 ^= x0; }
    TFR(13) TFR(15) TFR(26) TFR(6)
    x0 += k1; x1 += k2 + 1u;
    TFR(17) TFR(29) TFR(16) TFR(24)
    x0 += k2; x1 += k0 + 2u;
    TFR(13) TFR(15) TFR(26) TFR(6)
    x0 += k0; x1 += k1 + 3u;
    TFR(17) TFR(29) TFR(16) TFR(24)
    x0 += k1; x1 += k2 + 4u;
    TFR(13) TFR(15) TFR(26) TFR(6)
    x0 += k2; x1 += k0 + 5u;
#undef TFR
    U2 r; r.x = x0; r.y = x1; return r;
}

// Integer add on the FMA pipe: IMAD r = a*one + b, `one` is an opaque runtime 1.
__device__ __forceinline__ uint32_t addi(uint32_t a, uint32_t b, uint32_t one) {
    uint32_t r;
    asm("mad.lo.u32 %0, %1, %2, %3;" : "=r"(r) : "r"(a), "r"(one), "r"(b));
    return r;
}

// Cipher specialized for x0-start == 0 (partitionable counters). ALL adds
// (round adds + both key injections) go through IMAD (fma pipe); SHF/LOP3
// stay on alu. (Locally optimal schedule per R5/R11/R14/R15/R16 probes.)
__device__ __forceinline__ U2 tf_dev0(uint32_t x1, const TFK K, uint32_t one) {
    uint32_t x0 = K.a0;
    x1 = addi(x1, K.b0, one);
#define TFRD(r) { x0 = addi(x0, x1, one); x1 = rotl32(x1, r) ^ x0; }
    TFRD(13) TFRD(15) TFRD(26) TFRD(6)
    x0 = addi(x0, K.a1, one); x1 = addi(x1, K.b1, one);
    TFRD(17) TFRD(29) TFRD(16) TFRD(24)
    x0 = addi(x0, K.a2, one); x1 = addi(x1, K.b2, one);
    TFRD(13) TFRD(15) TFRD(26) TFRD(6)
    x0 = addi(x0, K.a3, one); x1 = addi(x1, K.b3, one);
    TFRD(17) TFRD(29) TFRD(16) TFRD(24)
    x0 = addi(x0, K.a4, one); x1 = addi(x1, K.b4, one);
    TFRD(13) TFRD(15) TFRD(26) TFRD(6)
    x0 = addi(x0, K.a5, one); x1 = addi(x1, K.b5, one);
#undef TFRD
    U2 r; r.x = x0; r.y = x1; return r;
}

// general device cipher (legacy path)
__device__ __forceinline__ U2 tf_dev(uint32_t x0, uint32_t x1, const TFK K, uint32_t one) {
#define TFRD(r) { x0 = addi(x0, x1, one); x1 = rotl32(x1, r) ^ x0; }
    x0 = addi(x0, K.a0, one); x1 = addi(x1, K.b0, one);
    TFRD(13) TFRD(15) TFRD(26) TFRD(6)
    x0 = addi(x0, K.a1, one); x1 = addi(x1, K.b1, one);
    TFRD(17) TFRD(29) TFRD(16) TFRD(24)
    x0 = addi(x0, K.a2, one); x1 = addi(x1, K.b2, one);
    TFRD(13) TFRD(15) TFRD(26) TFRD(6)
    x0 = addi(x0, K.a3, one); x1 = addi(x1, K.b3, one);
    TFRD(17) TFRD(29) TFRD(16) TFRD(24)
    x0 = addi(x0, K.a4, one); x1 = addi(x1, K.b4, one);
    TFRD(13) TFRD(15) TFRD(26) TFRD(6)
    x0 = addi(x0, K.a5, one); x1 = addi(x1, K.b5, one);
#undef TFRD
    U2 r; r.x = x0; r.y = x1; return r;
}

__device__ __forceinline__ float ex2a(float x) {
    float r; asm("ex2.approx.ftz.f32 %0, %1;" : "=f"(r) : "f"(x)); return r;
}
__device__ __forceinline__ float lg2a(float x) {
    float r; asm("lg2.approx.ftz.f32 %0, %1;" : "=f"(r) : "f"(x)); return r;
}

// Returns lg2(t), t = 1e-20 - ln(u + 1e-20); gumbel g = -ln2 * lg2(t).
// eps folded into the FMA constant (u + 1e-20 == u in fp32 for nonzero u).
// Poly branch keeps relative accuracy near u==1 where MUFU abs error blows up.
__device__ __forceinline__ float gumbel_lg2t(uint32_t bits, uint32_t one) {
    uint32_t hi = __umulhi(bits, 0x00800000u);           // bits >> 9
    float u = __uint_as_float(addi(hi, 0x3f800000u, one)) - 1.0f;
    float d = 1.0f - u;                        // exact (Sterbenz) for u >= 0.5
    float series = fmaf(d, fmaf(d, fmaf(d, 0.25f, 0.33333334f), 0.5f), 1.0f);
    float t_poly = fmaf(d, series, 1e-20f);    // 1e-20 - ln(1-d), |d|<=1/16
    float t_lf = fmaf(-0.6931471805599453f, lg2a(u), 1e-20f);
    float t = (d <= 0.0625f) ? t_poly : t_lf;  // > 0
    return lg2a(t);
}

__device__ __forceinline__ float bits_to_gumbel(uint32_t bits, uint32_t one) {
    return -0.6931471805599453f * gumbel_lg2t(bits, one);
}

__device__ __forceinline__ float warp_sum(float v) {
    #pragma unroll
    for (int o = 16; o; o >>= 1) v += __shfl_xor_sync(0xffffffffu, v, o);
    return v;
}
__device__ __forceinline__ float grp8_max(float v) {
    v = fmaxf(v, __shfl_xor_sync(0xffffffffu, v, 4));
    v = fmaxf(v, __shfl_xor_sync(0xffffffffu, v, 2));
    v = fmaxf(v, __shfl_xor_sync(0xffffffffu, v, 1));
    return v;
}
__device__ __forceinline__ float grp8_sum(float v) {
    v += __shfl_xor_sync(0xffffffffu, v, 4);
    v += __shfl_xor_sync(0xffffffffu, v, 2);
    v += __shfl_xor_sync(0xffffffffu, v, 1);
    return v;
}

// ---------------- shared-memory (read-only after init) ----------------
struct CoordSm {
    float4 grid[NC];     // 16000 B
    float  Ws[192];
    float  bs[64];
};
struct CodeSm {
    float  lwt[4096];       // 16384 B  [d][ke] transposed lin_ws
    float  emb_s[32 * 17];  //  2176 B
};

// =======================================================================
// One coordinate row-pair per warp. ILP x4 cipher chains; factorized
// first-softmax KL via shuffles; barrier-free. Returns kll+klh.
// =======================================================================
__device__ __forceinline__ float coord_pair(
    const CoordSm& sm, int rlo,
    const float* __restrict__ inputs, float* __restrict__ out,
    const TFK Kc, uint32_t one)
{
    const int lane = threadIdx.x & 31;
    const int rhi = rlo + HROWS;

    float p0l, p1l, p2l, ccl, p0h, p1h, p2h, cch;
    {
        float il0 = inputs[(size_t)rlo * 64 + lane];
        float il1 = inputs[(size_t)rlo * 64 + 32 + lane];
        float ih0 = inputs[(size_t)rhi * 64 + lane];
        float ih1 = inputs[(size_t)rhi * 64 + 32 + lane];
        float w00 = sm.Ws[lane * 3 + 0], w01 = sm.Ws[lane * 3 + 1], w02 = sm.Ws[lane * 3 + 2];
        float w10 = sm.Ws[(lane + 32) * 3 + 0], w11 = sm.Ws[(lane + 32) * 3 + 1], w12 = sm.Ws[(lane + 32) * 3 + 2];
        float b0 = sm.bs[lane], b1 = sm.bs[lane + 32];

        p0l = warp_sum(fmaf(il0, w00, il1 * w10));
        p1l = warp_sum(fmaf(il0, w01, il1 * w11));
        p2l = warp_sum(fmaf(il0, w02, il1 * w12));
        ccl = warp_sum(fmaf(il0, b0,  il1 * b1));
        p0h = warp_sum(fmaf(ih0, w00, ih1 * w10));
        p1h = warp_sum(fmaf(ih0, w01, ih1 * w11));
        p2h = warp_sum(fmaf(ih0, w02, ih1 * w12));
        cch = warp_sum(fmaf(ih0, b0,  ih1 * b1));
    }

    const float L2E  = 1.4426950408889634f;
    const float HL2E = 0.7213475204444817f;
    const float LN2  = 0.6931471805599453f;
    float M1l = ccl + 1.5f * (fmaxf(p0l, 0.f) + fmaxf(p1l, 0.f) + fmaxf(p2l, 0.f));
    float M1h = cch + 1.5f * (fmaxf(p0h, 0.f) + fmaxf(p1h, 0.f) + fmaxf(p2h, 0.f));

    // fully pre-scaled exponent: e2 = exp2(ps.g + cB - lt/2)
    float ps0l = p0l * HL2E, ps1l = p1l * HL2E, ps2l = p2l * HL2E;
    float ps0h = p0h * HL2E, ps1h = p1h * HL2E, ps2h = p2h * HL2E;
    float cBl = (ccl - M1l - 16.0f) * HL2E;
    float cBh = (cch - M1h - 16.0f) * HL2E;

    // ---- factorized logZ/KL: lanes 0..5 each handle one (row,dim);
    // shared afterwards by shuffles (no smem, no barrier) ----
    float fv = 0.0f;
    {
        int dim = lane >> 1;
        bool hiRow = lane & 1;
        float p = dim == 0 ? (hiRow ? p0h : p0l)
                : dim == 1 ? (hiRow ? p1h : p1l)
                           : (hiRow ? p2h : p2l);
        if (lane < 6) {
            float mx = 1.5f * fmaxf(p, 0.f);
            float P = 0.f, X = 0.f;
            #pragma unroll
            for (int t = 0; t < 10; t++) {
                float xs = (float)t * (float)(1.5 / 9.0);
                float e = ex2a((p * xs - mx) * L2E);
                P += e; X = fmaf(xs, e, X);
            }
            fv = p * (X / P) - LN2 * lg2a(P);   // E_dim - lnP_dim
        }
    }
    float f0 = __shfl_sync(0xffffffffu, fv, 0);
    float f1 = __shfl_sync(0xffffffffu, fv, 1);
    float f2 = __shfl_sync(0xffffffffu, fv, 2);
    float f3 = __shfl_sync(0xffffffffu, fv, 3);
    float f4 = __shfl_sync(0xffffffffu, fv, 4);
    float f5 = __shfl_sync(0xffffffffu, fv, 5);

    float S2l = 0.f, gxl = 0.f, gyl = 0.f, gzl = 0.f;
    float S2h = 0.f, gxh = 0.f, gyh = 0.f, gzh = 0.f;

    uint32_t ia1 = (uint32_t)rlo * 1000u + (uint32_t)lane;
    uint32_t ia2 = ia1 + 32u;
#if RNG_PARTITIONABLE
    uint32_t ib1 = ia1 + H_COORD;
    uint32_t ib2 = ib1 + 32u;
#endif

    // ---- 15 full iterations, no predicates (covers n in [0,960)) ----
    #pragma unroll 1
    for (int t = 0; t < 15; t++) {
        const int n  = lane + (t << 6);
        float4 g1 = sm.grid[n];
        float4 g2 = sm.grid[n + 32];

        float f1l = fmaf(ps0l, g1.x, fmaf(ps1l, g1.y, fmaf(ps2l, g1.z, cBl)));
        float f1h = fmaf(ps0h, g1.x, fmaf(ps1h, g1.y, fmaf(ps2h, g1.z, cBh)));
        float f2l = fmaf(ps0l, g2.x, fmaf(ps1l, g2.y, fmaf(ps2l, g2.z, cBl)));
        float f2h = fmaf(ps0h, g2.x, fmaf(ps1h, g2.y, fmaf(ps2h, g2.z, cBh)));

#if RNG_PARTITIONABLE
        U2 A1 = tf_dev0(ia1, Kc, one);
        U2 A2 = tf_dev0(ia2, Kc, one);
        U2 B1 = tf_dev0(ib1, Kc, one);
        U2 B2 = tf_dev0(ib2, Kc, one);
        float lt1l = gumbel_lg2t(A1.x ^ A1.y, one);
        float lt2l = gumbel_lg2t(A2.x ^ A2.y, one);
        float lt1h = gumbel_lg2t(B1.x ^ B1.y, one);
        float lt2h = gumbel_lg2t(B2.x ^ B2.y, one);
        ia1 = addi(ia1, 64u, one); ia2 = addi(ia2, 64u, one);
        ib1 = addi(ib1, 64u, one); ib2 = addi(ib2, 64u, one);
#else
        U2 A1 = tf_dev(ia1, ia1 + H_COORD, Kc, one);
        U2 A2 = tf_dev(ia2, ia2 + H_COORD, Kc, one);
        float lt1l = gumbel_lg2t(A1.x, one), lt1h = gumbel_lg2t(A1.y, one);
        float lt2l = gumbel_lg2t(A2.x, one), lt2h = gumbel_lg2t(A2.y, one);
        ia1 = addi(ia1, 64u, one); ia2 = addi(ia2, 64u, one);
#endif
        float e1l = ex2a(fmaf(lt1l, -0.5f, f1l));
        float e1h = ex2a(fmaf(lt1h, -0.5f, f1h));
        float e2l = ex2a(fmaf(lt2l, -0.5f, f2l));
        float e2h = ex2a(fmaf(lt2h, -0.5f, f2h));

        S2l += e1l; gxl = fmaf(e1l, g1.x, gxl); gyl = fmaf(e1l, g1.y, gyl); gzl = fmaf(e1l, g1.z, gzl);
        S2h += e1h; gxh = fmaf(e1h, g1.x, gxh); gyh = fmaf(e1h, g1.y, gyh); gzh = fmaf(e1h, g1.z, gzh);
        S2l += e2l; gxl = fmaf(e2l, g2.x, gxl); gyl = fmaf(e2l, g2.y, gyl); gzl = fmaf(e2l, g2.z, gzl);
        S2h += e2h; gxh = fmaf(e2h, g2.x, gxh); gyh = fmaf(e2h, g2.y, gyh); gzh = fmaf(e2h, g2.z, gzh);
    }

    // ---- tail: n in [960,1000): point1 always valid, point2 iff lane<8 ----
    {
        const int n = lane + 960;
        const bool v2 = (lane < 8);
        float4 g1 = sm.grid[n];
        float4 g2 = sm.grid[v2 ? (n + 32) : n];

        float f1l = fmaf(ps0l, g1.x, fmaf(ps1l, g1.y, fmaf(ps2l, g1.z, cBl)));
        float f1h = fmaf(ps0h, g1.x, fmaf(ps1h, g1.y, fmaf(ps2h, g1.z, cBh)));
        float f2l = fmaf(ps0l, g2.x, fmaf(ps1l, g2.y, fmaf(ps2l, g2.z, cBl)));
        float f2h = fmaf(ps0h, g2.x, fmaf(ps1h, g2.y, fmaf(ps2h, g2.z, cBh)));

#if RNG_PARTITIONABLE
        U2 A1 = tf_dev0(ia1, Kc, one);
        U2 A2 = tf_dev0(ia2, Kc, one);
        U2 B1 = tf_dev0(ib1, Kc, one);
        U2 B2 = tf_dev0(ib2, Kc, one);
        float lt1l = gumbel_lg2t(A1.x ^ A1.y, one);
        float lt2l = gumbel_lg2t(A2.x ^ A2.y, one);
        float lt1h = gumbel_lg2t(B1.x ^ B1.y, one);
        float lt2h = gumbel_lg2t(B2.x ^ B2.y, one);
#else
        U2 A1 = tf_dev(ia1, ia1 + H_COORD, Kc, one);
        U2 A2 = tf_dev(ia2, ia2 + H_COORD, Kc, one);
        float lt1l = gumbel_lg2t(A1.x, one), lt1h = gumbel_lg2t(A1.y, one);
        float lt2l = gumbel_lg2t(A2.x, one), lt2h = gumbel_lg2t(A2.y, one);
#endif
        float e1l = ex2a(fmaf(lt1l, -0.5f, f1l));
        float e1h = ex2a(fmaf(lt1h, -0.5f, f1h));
        float e2l = ex2a(fmaf(lt2l, -0.5f, f2l));
        float e2h = ex2a(fmaf(lt2h, -0.5f, f2h));
        if (!v2) { e2l = 0.f; e2h = 0.f; }

        S2l += e1l; gxl = fmaf(e1l, g1.x, gxl); gyl = fmaf(e1l, g1.y, gyl); gzl = fmaf(e1l, g1.z, gzl);
        S2h += e1h; gxh = fmaf(e1h, g1.x, gxh); gyh = fmaf(e1h, g1.y, gyh); gzh = fmaf(e1h, g1.z, gzh);
        S2l += e2l; gxl = fmaf(e2l, g2.x, gxl); gyl = fmaf(e2l, g2.y, gyl); gzl = fmaf(e2l, g2.z, gzl);
        S2h += e2h; gxh = fmaf(e2h, g2.x, gxh); gyh = fmaf(e2h, g2.y, gyh); gzh = fmaf(e2h, g2.z, gzh);
    }

    S2l = warp_sum(S2l); gxl = warp_sum(gxl); gyl = warp_sum(gyl); gzl = warp_sum(gzl);
    S2h = warp_sum(S2h); gxh = warp_sum(gxh); gyh = warp_sum(gyh); gzh = warp_sum(gzh);

    float kll = ccl + f0 + f2 + f4 - M1l + 6.907755278982137f;
    float klh = cch + f1 + f3 + f5 - M1h + 6.907755278982137f;

    float invl = 1.0f / S2l, invh = 1.0f / S2h;
    gxl *= invl; gyl *= invl; gzl *= invl;
    gxh *= invh; gyh *= invh; gzh *= invh;

    {
        float w00 = sm.Ws[lane * 3 + 0], w01 = sm.Ws[lane * 3 + 1], w02 = sm.Ws[lane * 3 + 2];
        float w10 = sm.Ws[(lane + 32) * 3 + 0], w11 = sm.Ws[(lane + 32) * 3 + 1], w12 = sm.Ws[(lane + 32) * 3 + 2];
        float b0 = sm.bs[lane], b1 = sm.bs[lane + 32];
        out[QCOFF + (size_t)rlo * 64 + lane]      = fmaf(w00, gxl, fmaf(w01, gyl, fmaf(w02, gzl, b0)));
        out[QCOFF + (size_t)rlo * 64 + 32 + lane] = fmaf(w10, gxl, fmaf(w11, gyl, fmaf(w12, gzl, b1)));
        out[QCOFF + (size_t)rhi * 64 + lane]      = fmaf(w00, gxh, fmaf(w01, gyh, fmaf(w02, gzh, b0)));
        out[QCOFF + (size_t)rhi * 64 + 32 + lane] = fmaf(w10, gxh, fmaf(w11, gyh, fmaf(w12, gzh, b1)));
    }
    return kll + klh;
}

// =======================================================================
// One per-codebook row-pair per warp (~7% of the work). Barrier-free.
// =======================================================================
__device__ __forceinline__ float code_pair(
    const CodeSm& sm, int rlo,
    const float* __restrict__ inputs, float* __restrict__ out,
    const TFK Kp, uint32_t one)
{
    const int lane = threadIdx.x & 31;
    const int rhi = rlo + HROWS;

    float in0l = inputs[(size_t)rlo * 64 + lane];
    float in1l = inputs[(size_t)rlo * 64 + 32 + lane];
    float in0h = inputs[(size_t)rhi * 64 + lane];
    float in1h = inputs[(size_t)rhi * 64 + 32 + lane];

    float hl0 = 0.f, hl1 = 0.f, hh0 = 0.f, hh1 = 0.f;
    const float2* lwt2 = reinterpret_cast<const float2*>(sm.lwt);
    #pragma unroll 8
    for (int d = 0; d < 32; d++) {
        float xl = __shfl_sync(0xffffffffu, in0l, d);
        float xh = __shfl_sync(0xffffffffu, in0h, d);
        float2 wv = lwt2[d * 32 + lane];
        hl0 = fmaf(xl, wv.x, hl0); hl1 = fmaf(xl, wv.y, hl1);
        hh0 = fmaf(xh, wv.x, hh0); hh1 = fmaf(xh, wv.y, hh1);
    }
    #pragma unroll 8
    for (int d = 0; d < 32; d++) {
        float xl = __shfl_sync(0xffffffffu, in1l, d);
        float xh = __shfl_sync(0xffffffffu, in1h, d);
        float2 wv = lwt2[(d + 32) * 32 + lane];
        hl0 = fmaf(xl, wv.x, hl0); hl1 = fmaf(xl, wv.y, hl1);
        hh0 = fmaf(xh, wv.x, hh0); hh1 = fmaf(xh, wv.y, hh1);
    }

    const int kk = lane >> 3;
    float xpl = 0.f, xph = 0.f;
    #pragma unroll
    for (int e2 = 0; e2 < 8; e2++) {
        int src = kk * 8 + e2;
        float a0l = __shfl_sync(0xffffffffu, hl0, src);
        float a1l = __shfl_sync(0xffffffffu, hl1, src);
        float a0h = __shfl_sync(0xffffffffu, hh0, src);
        float a1h = __shfl_sync(0xffffffffu, hh1, src);
        float ev0 = sm.emb_s[lane * 17 + 2 * e2];
        float ev1 = sm.emb_s[lane * 17 + 2 * e2 + 1];
        xpl = fmaf(a0l, ev0, fmaf(a1l, ev1, xpl));
        xph = fmaf(a0h, ev0, fmaf(a1h, ev1, xph));
    }

    float ml = grp8_max(xpl), mh = grp8_max(xph);
    float el = ex2a((xpl - ml) * 1.4426950408889634f);
    float eh = ex2a((xph - mh) * 1.4426950408889634f);
    float sl = grp8_sum(el), sh2 = grp8_sum(eh);
    float lzl = fmaf(0.6931471805599453f, lg2a(sl), ml);
    float lzh = fmaf(0.6931471805599453f, lg2a(sh2), mh);
    float lpl = xpl - lzl, lph = xph - lzh;
    float kl_l = grp8_sum(el * (lpl + 2.0794415416798357f)) / sl;
    float kl_h = grp8_sum(eh * (lph + 2.0794415416798357f)) / sh2;

    uint32_t idx = (uint32_t)rlo * 32u + (uint32_t)lane;
    float gl, gh;
#if RNG_PARTITIONABLE
    U2 A = tf_dev0(idx, Kp, one);
    U2 B = tf_dev0(idx + H_CODE, Kp, one);
    gl = bits_to_gumbel(A.x ^ A.y, one);
    gh = bits_to_gumbel(B.x ^ B.y, one);
#else
    U2 A = tf_dev(idx, idx + H_CODE, Kp, one);
    gl = bits_to_gumbel(A.x, one);
    gh = bits_to_gumbel(A.y, one);
#endif

    float zl = (lpl + gl) * 0.5f, zh = (lph + gh) * 0.5f;
    float m2l = grp8_max(zl), m2h = grp8_max(zh);
    float e2l = ex2a((zl - m2l) * 1.4426950408889634f);
    float e2h = ex2a((zh - m2h) * 1.4426950408889634f);
    float s2l = grp8_sum(e2l), s2h = grp8_sum(e2h);
    float ipl = e2l / s2l, iph = e2h / s2h;

    const int k2 = lane >> 3;
    const int e0 = (2 * lane) & 15;
    float ql0 = 0.f, ql1 = 0.f, qh0 = 0.f, qh1 = 0.f;
    #pragma unroll
    for (int nn = 0; nn < 8; nn++) {
        int src = k2 * 8 + nn;
        float wl = __shfl_sync(0xffffffffu, ipl, src);
        float wh = __shfl_sync(0xffffffffu, iph, src);
        float ev0 = sm.emb_s[src * 17 + e0];
        float ev1 = sm.emb_s[src * 17 + e0 + 1];
        ql0 = fmaf(wl, ev0, ql0); ql1 = fmaf(wl, ev1, ql1);
        qh0 = fmaf(wh, ev0, qh0); qh1 = fmaf(wh, ev1, qh1);
    }
    float2* o2 = reinterpret_cast<float2*>(out);
    o2[(size_t)rlo * 32 + lane] = make_float2(ql0, ql1);
    o2[(size_t)rhi * 32 + lane] = make_float2(qh0, qh1);

    float klrow = ((lane & 7) == 0) ? (kl_l + kl_h) : 0.0f;
    return warp_sum(klrow);
}

// Persistent, warp-independent fused kernel (the R12 champion). After the
// one-time smem init (read-only thereafter) there are NO block barriers:
// each warp owns a static strided set of coord row-pairs then code
// row-pairs, accumulating its KL partial in a register double. Last block
// reduces the loss.
__global__ void __launch_bounds__(256, 4)
k_fused(const float* __restrict__ inputs, const float* __restrict__ linear_w,
        const float* __restrict__ linear_b, const float* __restrict__ emb,
        const float* __restrict__ lin_ws, float* __restrict__ out,
        TFK Kc, TFK Kp, uint32_t one, int loss_idx)
{
    __shared__ CoordSm smc;
    __shared__ CodeSm smq;
    __shared__ int is_last;
    const int tid = threadIdx.x;

    // one-time smem setup for BOTH work types
    for (int i = tid; i < 192; i += 256) smc.Ws[i] = linear_w[i];
    for (int i = tid; i < 64;  i += 256) smc.bs[i] = linear_b[i];
    for (int n = tid; n < NC; n += 256) {
        int i10 = n / 100, j10 = (n / 10) % 10, k10 = n % 10;
        // meshgrid 'xy': g[n] = (x[j], x[i], x[k])
        smc.grid[n] = make_float4((float)(j10 * (1.5 / 9.0)),
                                  (float)(i10 * (1.5 / 9.0)),
                                  (float)(k10 * (1.5 / 9.0)), 0.0f);
    }
    for (int i = tid; i < 4096; i += 256) {
        int ke = i >> 6, d = i & 63;
        smq.lwt[d * 64 + ke] = lin_ws[i];
    }
    for (int i = tid; i < 512; i += 256)
        smq.emb_s[(i >> 4) * 17 + (i & 15)] = emb[i];
    __syncthreads();   // the ONLY block barrier before the final reduction

    const int gw = blockIdx.x * 8 + (tid >> 5);   // global warp id
    double klacc = 0.0;

    // coord row-pairs: rlo in [0, HROWS), strided by NWARP
    for (int rlo = gw; rlo < HROWS; rlo += NWARP)
        klacc += (double)coord_pair(smc, rlo, inputs, out, Kc, one);

    // code row-pairs
    for (int rlo = gw; rlo < HROWS; rlo += NWARP)
        klacc += (double)code_pair(smq, rlo, inputs, out, Kp, one);

    if ((tid & 31) == 0) g_parts[gw] = klacc;

    __threadfence();
    __syncthreads();
    if (tid == 0) {
        unsigned int prev = atomicAdd(&g_done, 1u);
        is_last = (prev == gridDim.x - 1u);
    }
    __syncthreads();
    if (is_last) {
        double* red = reinterpret_cast<double*>(&smc);   // reuse smem
        double s = 0;
        for (int i = tid; i < NWARP; i += 256) s += g_parts[i];
        red[tid] = s;
        __syncthreads();
        #pragma unroll
        for (int o = 128; o; o >>= 1) {
            if (tid < o) red[tid] += red[tid + o];
            __syncthreads();
        }
        if (tid == 0) {
            out[loss_idx] = (float)(red[0] / 5.0);
            g_done = 0;   // reset for next graph replay
        }
    }
}

extern "C" void kernel_launch(void* const* d_in, const int* in_sizes, int n_in,
                              void* d_out, int out_size) {
    const float* inputs   = (const float*)d_in[0];
    const float* linear_w = (const float*)d_in[1];
    const float* linear_b = (const float*)d_in[2];
    const float* emb      = (const float*)d_in[3];
    const float* lin_ws   = (const float*)d_in[4];
    float* out = (float*)d_out;

    // kc, kp = jax.random.split(jax.random.key(42))
#if RNG_PARTITIONABLE
    U2 a = tf_host(0u, 42u, 0u, 0u);
    U2 b = tf_host(0u, 42u, 0u, 1u);
    uint32_t kc0 = a.x, kc1 = a.y;
    uint32_t kp0 = b.x, kp1 = b.y;
#else
    U2 a = tf_host(0u, 42u, 0u, 2u);
    U2 b = tf_host(0u, 42u, 1u, 3u);
    uint32_t kc0 = a.x, kc1 = b.x;
    uint32_t kp0 = a.y, kp1 = b.y;
#endif
    TFK Kc = make_tfk(kc0, kc1);
    TFK Kp = make_tfk(kp0, kp1);

    k_fused<<<NBLK, 256>>>(inputs, linear_w, linear_b, emb, lin_ws, out,
                           Kc, Kp, 1u, out_size - 1);
}